// round 4
// baseline (speedup 1.0000x reference)
#include <cuda_runtime.h>
#include <cuda_bf16.h>

// CBOW negative-sampling loss.
// Inputs (metadata order):
//   d_in[0] i_emb        float32  (VOCAB+1, 50)
//   d_in[1] o_emb        float32  (VOCAB+1, 50)
//   d_in[2] target_wids  int32    (B,)
//   d_in[3] context_wids int32    (B, 10)
//   d_in[4] neg_wids     int32    (B, 10)
// Output: scalar float32 = -( sum log_sigmoid(pos) + sum log_sigmoid(-neg) )

#define DIM  50
#define CTX  10
#define NNEG 10

__device__ double g_accum;

__device__ __forceinline__ float log_sigmoid(float x) {
    // numerically stable: min(x,0) - log1p(exp(-|x|))
    return fminf(x, 0.0f) - log1pf(__expf(-fabsf(x)));
}

__global__ void cbow_zero_kernel() {
    g_accum = 0.0;
}

__global__ void __launch_bounds__(256) cbow_main_kernel(
    const float* __restrict__ i_emb,
    const float* __restrict__ o_emb,
    const int*   __restrict__ target_wids,
    const int*   __restrict__ context_wids,
    const int*   __restrict__ neg_wids,
    int B)
{
    const int warp_global = (blockIdx.x * blockDim.x + threadIdx.x) >> 5;
    const int lane        = threadIdx.x & 31;
    const int warp_local  = threadIdx.x >> 5;

    __shared__ float s_partial[8];

    float loss = 0.0f;

    if (warp_global < B) {
        const int  d0     = lane;        // always < 50
        const int  d1     = lane + 32;   // valid iff lane < 18
        const bool has_d1 = (d1 < DIM);

        // ---- average context embedding (registers, per-lane 2 dims) ----
        const int* __restrict__ cw = context_wids + warp_global * CTX;
        float a0 = 0.0f, a1 = 0.0f;
        #pragma unroll
        for (int c = 0; c < CTX; c++) {
            const long base = (long)__ldg(&cw[c]) * DIM;
            a0 += __ldg(&i_emb[base + d0]);
            if (has_d1) a1 += __ldg(&i_emb[base + d1]);
        }
        a0 *= (1.0f / CTX);
        a1 *= (1.0f / CTX);

        // ---- positive score ----
        {
            const long base = (long)__ldg(&target_wids[warp_global]) * DIM;
            float p = __ldg(&o_emb[base + d0]) * a0;
            if (has_d1) p = fmaf(__ldg(&o_emb[base + d1]), a1, p);
            #pragma unroll
            for (int o = 16; o > 0; o >>= 1)
                p += __shfl_xor_sync(0xFFFFFFFFu, p, o);
            loss += log_sigmoid(p);
        }

        // ---- negative scores ----
        const int* __restrict__ nw = neg_wids + warp_global * NNEG;
        #pragma unroll
        for (int n = 0; n < NNEG; n++) {
            const long base = (long)__ldg(&nw[n]) * DIM;
            float p = __ldg(&o_emb[base + d0]) * a0;
            if (has_d1) p = fmaf(__ldg(&o_emb[base + d1]), a1, p);
            #pragma unroll
            for (int o = 16; o > 0; o >>= 1)
                p += __shfl_xor_sync(0xFFFFFFFFu, p, o);
            loss += log_sigmoid(-p);
        }
    }

    // After the xor-butterfly, every lane of a warp holds the identical full
    // sum; lane 0 deposits it.
    if (lane == 0) s_partial[warp_local] = loss;
    __syncthreads();

    if (threadIdx.x == 0) {
        float blk = 0.0f;
        #pragma unroll
        for (int i = 0; i < 8; i++) blk += s_partial[i];
        atomicAdd(&g_accum, (double)blk);
    }
}

__global__ void cbow_finish_kernel(float* __restrict__ out) {
    out[0] = (float)(-g_accum);
}

extern "C" void kernel_launch(void* const* d_in, const int* in_sizes, int n_in,
                              void* d_out, int out_size)
{
    const float* i_emb       = (const float*)d_in[0];
    const float* o_emb       = (const float*)d_in[1];
    const int*   target_wids = (const int*)d_in[2];
    const int*   context_wids= (const int*)d_in[3];
    const int*   neg_wids    = (const int*)d_in[4];
    float*       out         = (float*)d_out;

    const int B = in_sizes[2];                 // number of batch rows
    const int warps_per_block = 256 / 32;      // 8
    const int blocks = (B + warps_per_block - 1) / warps_per_block;

    cbow_zero_kernel<<<1, 1>>>();
    cbow_main_kernel<<<blocks, 256>>>(i_emb, o_emb, target_wids,
                                      context_wids, neg_wids, B);
    cbow_finish_kernel<<<1, 1>>>(out);
}

// round 5
// speedup vs baseline: 1.0107x; 1.0107x over previous
#include <cuda_runtime.h>
#include <cuda_bf16.h>

// CBOW negative-sampling loss.
// Inputs (metadata order):
//   d_in[0] i_emb        float32  (VOCAB+1, 50)
//   d_in[1] o_emb        float32  (VOCAB+1, 50)
//   d_in[2] target_wids  int32    (B,)
//   d_in[3] context_wids int32    (B, 10)
//   d_in[4] neg_wids     int32    (B, 10)
// Output: scalar float32 = -( sum log_sigmoid(pos) + sum log_sigmoid(-neg) )

#define DIM  50
#define CTX  10
#define NNEG 10

__device__ double g_accum;

__device__ __forceinline__ float log_sigmoid(float x) {
    // numerically stable: min(x,0) - log1p(exp(-|x|))
    return fminf(x, 0.0f) - log1pf(__expf(-fabsf(x)));
}

__global__ void cbow_zero_kernel() {
    g_accum = 0.0;
}

__global__ void __launch_bounds__(256) cbow_main_kernel(
    const float* __restrict__ i_emb,
    const float* __restrict__ o_emb,
    const int*   __restrict__ target_wids,
    const int*   __restrict__ context_wids,
    const int*   __restrict__ neg_wids,
    int B)
{
    const int warp_global = (blockIdx.x * blockDim.x + threadIdx.x) >> 5;
    const int lane        = threadIdx.x & 31;
    const int warp_local  = threadIdx.x >> 5;

    __shared__ float s_partial[8];

    float loss = 0.0f;

    if (warp_global < B) {
        const int  d0     = lane;        // always < 50
        const int  d1     = lane + 32;   // valid iff lane < 18
        const bool has_d1 = (d1 < DIM);

        // ---- average context embedding (registers, per-lane 2 dims) ----
        const int* __restrict__ cw = context_wids + warp_global * CTX;
        float a0 = 0.0f, a1 = 0.0f;
        #pragma unroll
        for (int c = 0; c < CTX; c++) {
            const long base = (long)__ldg(&cw[c]) * DIM;
            a0 += __ldg(&i_emb[base + d0]);
            if (has_d1) a1 += __ldg(&i_emb[base + d1]);
        }
        a0 *= (1.0f / CTX);
        a1 *= (1.0f / CTX);

        // ---- positive score ----
        {
            const long base = (long)__ldg(&target_wids[warp_global]) * DIM;
            float p = __ldg(&o_emb[base + d0]) * a0;
            if (has_d1) p = fmaf(__ldg(&o_emb[base + d1]), a1, p);
            #pragma unroll
            for (int o = 16; o > 0; o >>= 1)
                p += __shfl_xor_sync(0xFFFFFFFFu, p, o);
            loss += log_sigmoid(p);
        }

        // ---- negative scores ----
        const int* __restrict__ nw = neg_wids + warp_global * NNEG;
        #pragma unroll
        for (int n = 0; n < NNEG; n++) {
            const long base = (long)__ldg(&nw[n]) * DIM;
            float p = __ldg(&o_emb[base + d0]) * a0;
            if (has_d1) p = fmaf(__ldg(&o_emb[base + d1]), a1, p);
            #pragma unroll
            for (int o = 16; o > 0; o >>= 1)
                p += __shfl_xor_sync(0xFFFFFFFFu, p, o);
            loss += log_sigmoid(-p);
        }
    }

    // After the xor-butterfly, every lane of a warp holds the identical full
    // sum; lane 0 deposits it.
    if (lane == 0) s_partial[warp_local] = loss;
    __syncthreads();

    if (threadIdx.x == 0) {
        float blk = 0.0f;
        #pragma unroll
        for (int i = 0; i < 8; i++) blk += s_partial[i];
        atomicAdd(&g_accum, (double)blk);
    }
}

__global__ void cbow_finish_kernel(float* __restrict__ out) {
    out[0] = (float)(-g_accum);
}

extern "C" void kernel_launch(void* const* d_in, const int* in_sizes, int n_in,
                              void* d_out, int out_size)
{
    const float* i_emb       = (const float*)d_in[0];
    const float* o_emb       = (const float*)d_in[1];
    const int*   target_wids = (const int*)d_in[2];
    const int*   context_wids= (const int*)d_in[3];
    const int*   neg_wids    = (const int*)d_in[4];
    float*       out         = (float*)d_out;

    const int B = in_sizes[2];                 // number of batch rows
    const int warps_per_block = 256 / 32;      // 8
    const int blocks = (B + warps_per_block - 1) / warps_per_block;

    cbow_zero_kernel<<<1, 1>>>();
    cbow_main_kernel<<<blocks, 256>>>(i_emb, o_emb, target_wids,
                                      context_wids, neg_wids, B);
    cbow_finish_kernel<<<1, 1>>>(out);
}

// round 7
// speedup vs baseline: 1.1488x; 1.1367x over previous
#include <cuda_runtime.h>
#include <cuda_bf16.h>

// CBOW negative-sampling loss — single fused kernel.
// Inputs (metadata order):
//   d_in[0] i_emb        float32  (VOCAB+1, 50)
//   d_in[1] o_emb        float32  (VOCAB+1, 50)
//   d_in[2] target_wids  int32    (B,)
//   d_in[3] context_wids int32    (B, 10)
//   d_in[4] neg_wids     int32    (B, 10)
// Output: scalar float32 = -( sum log_sigmoid(pos) + sum log_sigmoid(-neg) )
//
// One warp per batch row. Rows are 50 floats = 200 B, 8B-aligned, so lanes
// 0..24 each load one float2 (LDG.64) -> one warp-load per row gather
// (21 gathers/row). Scores are reduced pairwise: one xor-16 exchange routes
// two scores into the two half-warps, then 4 butterfly steps reduce both.
// Block partials go through a last-block-reduces ticket so the whole problem
// is ONE graph-captured launch.

#define DIM2 25    // 50 floats = 25 float2
#define CTX  10
#define NNEG 10
#define MAX_BLOCKS 8192

__device__ float        g_partials[MAX_BLOCKS];
__device__ unsigned int g_count = 0;   // module-load init; reset by last block

__device__ __forceinline__ float log_sigmoid(float x) {
    // numerically stable: min(x,0) - log1p(exp(-|x|))
    return fminf(x, 0.0f) - log1pf(__expf(-fabsf(x)));
}

// Reduce two independent per-lane partials A,B across the warp in 5 shfls.
// Post: lane 0 holds full sum of A; lane 16 holds full sum of B.
__device__ __forceinline__ float pair_reduce(float A, float B, int lane) {
    float x = (lane & 16) ? A : B;                    // send the other half's score
    float y = __shfl_xor_sync(0xFFFFFFFFu, x, 16);
    float v = ((lane & 16) ? B : A) + y;              // each half now owns one score
    v += __shfl_xor_sync(0xFFFFFFFFu, v, 8);
    v += __shfl_xor_sync(0xFFFFFFFFu, v, 4);
    v += __shfl_xor_sync(0xFFFFFFFFu, v, 2);
    v += __shfl_xor_sync(0xFFFFFFFFu, v, 1);
    return v;
}

__global__ void __launch_bounds__(256) cbow_fused_kernel(
    const float* __restrict__ i_emb,
    const float* __restrict__ o_emb,
    const int*   __restrict__ target_wids,
    const int*   __restrict__ context_wids,
    const int*   __restrict__ neg_wids,
    float*       __restrict__ out,
    int B)
{
    const int warp_global = (blockIdx.x * blockDim.x + threadIdx.x) >> 5;
    const int lane        = threadIdx.x & 31;
    const int warp_local  = threadIdx.x >> 5;

    __shared__ float  s_partial[8];
    __shared__ int    s_is_last;
    __shared__ double s_d[8];

    float loss = 0.0f;   // nonzero only in lanes 0 and 16 after reductions

    if (warp_global < B) {
        const float2* __restrict__ i2 = (const float2*)i_emb;
        const float2* __restrict__ o2 = (const float2*)o_emb;
        const int*    __restrict__ cw = context_wids + warp_global * CTX;
        const int*    __restrict__ nw = neg_wids     + warp_global * NNEG;

        // ---- sum of context embeddings (unscaled; fold 1/CTX into score) ----
        float ax = 0.0f, ay = 0.0f;
        float p[NNEG + 1];
        #pragma unroll
        for (int k = 0; k <= NNEG; k++) p[k] = 0.0f;

        if (lane < DIM2) {
            #pragma unroll
            for (int c = 0; c < CTX; c++) {
                const long base = (long)__ldg(&cw[c]) * DIM2;
                const float2 e  = __ldg(&i2[base + lane]);
                ax += e.x;  ay += e.y;
            }

            // ---- per-lane partial dot products (11 scores) ----
            {
                const long base = (long)__ldg(&target_wids[warp_global]) * DIM2;
                const float2 e  = __ldg(&o2[base + lane]);
                p[0] = e.x * ax + e.y * ay;
            }
            #pragma unroll
            for (int n = 0; n < NNEG; n++) {
                const long base = (long)__ldg(&nw[n]) * DIM2;
                const float2 e  = __ldg(&o2[base + lane]);
                p[n + 1] = e.x * ax + e.y * ay;
            }
        }

        const float inv_ctx = 1.0f / CTX;

        // pair 0: (pos, neg0) — mixed signs
        {
            float v = pair_reduce(p[0], p[1], lane);
            if ((lane & 15) == 0) {
                float sc = v * inv_ctx;
                loss += log_sigmoid((lane & 16) ? -sc : sc);
            }
        }
        // pairs (neg1,neg2) (neg3,neg4) (neg5,neg6) (neg7,neg8)
        #pragma unroll
        for (int k = 2; k <= 8; k += 2) {
            float v = pair_reduce(p[k], p[k + 1], lane);
            if ((lane & 15) == 0)
                loss += log_sigmoid(-v * inv_ctx);
        }
        // leftover neg9: plain butterfly, accumulate at lane 0 only
        {
            float v = p[10];
            #pragma unroll
            for (int o = 16; o > 0; o >>= 1)
                v += __shfl_xor_sync(0xFFFFFFFFu, v, o);
            if (lane == 0)
                loss += log_sigmoid(-v * inv_ctx);
        }
    }

    // combine lanes 0 and 16
    loss += __shfl_xor_sync(0xFFFFFFFFu, loss, 16);
    if (lane == 0) s_partial[warp_local] = loss;
    __syncthreads();

    // block partial + last-block ticket
    if (threadIdx.x == 0) {
        float blk = 0.0f;
        #pragma unroll
        for (int i = 0; i < 8; i++) blk += s_partial[i];
        g_partials[blockIdx.x] = blk;
        __threadfence();
        unsigned int old = atomicAdd(&g_count, 1u);
        s_is_last = (old == gridDim.x - 1);
    }
    __syncthreads();

    if (s_is_last) {
        const int nb = gridDim.x;
        // Writers fenced before the ticket; volatile reads complete the
        // release/acquire pairing (classic threadFenceReduction pattern).
        volatile float* vp = g_partials;
        double acc = 0.0;
        for (int i = threadIdx.x; i < nb; i += 256)
            acc += (double)vp[i];
        #pragma unroll
        for (int o = 16; o > 0; o >>= 1)
            acc += __shfl_xor_sync(0xFFFFFFFFu, acc, o);
        if ((threadIdx.x & 31) == 0) s_d[threadIdx.x >> 5] = acc;
        __syncthreads();
        if (threadIdx.x == 0) {
            double t = 0.0;
            #pragma unroll
            for (int i = 0; i < 8; i++) t += s_d[i];
            out[0] = (float)(-t);
            g_count = 0;   // reset for next (graph-replayed) launch
        }
    }
}

extern "C" void kernel_launch(void* const* d_in, const int* in_sizes, int n_in,
                              void* d_out, int out_size)
{
    const float* i_emb        = (const float*)d_in[0];
    const float* o_emb        = (const float*)d_in[1];
    const int*   target_wids  = (const int*)d_in[2];
    const int*   context_wids = (const int*)d_in[3];
    const int*   neg_wids     = (const int*)d_in[4];
    float*       out          = (float*)d_out;

    const int B = in_sizes[2];
    const int warps_per_block = 256 / 32;   // 8
    int blocks = (B + warps_per_block - 1) / warps_per_block;
    if (blocks > MAX_BLOCKS) blocks = MAX_BLOCKS;   // fixed problem: B=16384 -> 2048

    cbow_fused_kernel<<<blocks, 256>>>(i_emb, o_emb, target_wids,
                                       context_wids, neg_wids, out, B);
}